// round 1
// baseline (speedup 1.0000x reference)
#include <cuda_runtime.h>
#include <cuda_bf16.h>
#include <cstdint>

#define NROWS 8192
#define DDIM  1024
#define KCLS  80
#define C81   81
#define MSEL  2048
#define TOPK  100
#define NFLAT (NROWS*KCLS)
#define SCORE_T 0.05f
#define SCALE_CLAMP 4.135166556742356f
#define IMG_W 1216.0f
#define IMG_H 800.0f
#define MAX_COORD 1217.0f
#define EQ_CAP 8192

// ---------------- scratch (all static __device__: no allocations) ----------------
__device__ float              g_probs[NFLAT];          // softmax probs (bg dropped)
__device__ unsigned long long g_cand[NFLAT];           // (u<<32)|idx for prob> T
__device__ int                g_hist1[65536];
__device__ int                g_hist2[65536];
__device__ unsigned long long g_sel[MSEL];             // sort keys (~m<<32)|idx
__device__ unsigned           g_eq[EQ_CAP];
__device__ float              g_boxes[MSEL*4];
__device__ float              g_obox[MSEL*4];
__device__ float              g_score[MSEL];
__device__ int                g_cls[MSEL];
__device__ unsigned char      g_sup[MSEL];
__device__ unsigned char      g_valid[MSEL];
__device__ int d_nCand, d_B, d_nAbove, d_r, d_nEq, d_nSel;
__device__ unsigned d_uCut;

// ---------------- helpers ----------------
__device__ __forceinline__ float wmaxf(float v){
    #pragma unroll
    for (int o=16;o;o>>=1) v = fmaxf(v, __shfl_xor_sync(0xffffffffu, v, o));
    return v;
}
__device__ __forceinline__ float wsumf(float v){
    #pragma unroll
    for (int o=16;o;o>>=1) v += __shfl_xor_sync(0xffffffffu, v, o);
    return v;
}

// ---------------- K0: reset ----------------
__global__ void k_reset(float* out, int out_size){
    int i = blockIdx.x*blockDim.x + threadIdx.x;
    if (i < 65536){ g_hist1[i]=0; g_hist2[i]=0; }
    if (i < MSEL)  g_sup[i]=0;
    if (i < out_size) out[i]=0.0f;
    if (i == 0){ d_nCand=0; d_nSel=0; d_nEq=0; d_r=0; d_B=-2; d_nAbove=0; d_uCut=0; }
}

// ---------------- K1: cls GEMM + softmax + histogram + candidate append ----------------
// block: 256 thr (8 warps x 32 lanes). tile: 64 rows x 81 cols. warp w owns rows w*8..w*8+7.
__global__ __launch_bounds__(256) void k_gemm_softmax(
    const float* __restrict__ x, const float* __restrict__ w, const float* __restrict__ b)
{
    __shared__ float xs[64][33];
    __shared__ float ws[32][81];
    const int tid = threadIdx.x;
    const int ty = tid >> 5, tx = tid & 31;
    const int row0 = blockIdx.x * 64;
    const bool has2 = (tx < 17);   // third col index tx+64 valid (<=80)

    float acc[8][3];
    #pragma unroll
    for (int r=0;r<8;r++){ acc[r][0]=0.f; acc[r][1]=0.f; acc[r][2]=0.f; }

    for (int kc=0; kc<DDIM; kc+=32){
        __syncthreads();
        #pragma unroll
        for (int i=tid; i<64*32; i+=256){
            int r=i>>5, k=i&31;
            xs[r][k] = x[(size_t)(row0+r)*DDIM + kc + k];
        }
        #pragma unroll
        for (int i=tid; i<32*81; i+=256){
            int k=i/81, c=i-k*81;
            ws[k][c] = w[(size_t)(kc+k)*C81 + c];
        }
        __syncthreads();
        #pragma unroll
        for (int k=0;k<32;k++){
            float b0 = ws[k][tx];
            float b1 = ws[k][tx+32];
            float b2 = has2 ? ws[k][tx+64] : 0.f;
            #pragma unroll
            for (int r=0;r<8;r++){
                float a = xs[ty*8+r][k];
                acc[r][0] = fmaf(a, b0, acc[r][0]);
                acc[r][1] = fmaf(a, b1, acc[r][1]);
                acc[r][2] = fmaf(a, b2, acc[r][2]);
            }
        }
    }

    const float bb0 = b[tx], bb1 = b[tx+32];
    const float bb2 = has2 ? b[tx+64] : 0.f;

    #pragma unroll
    for (int r=0;r<8;r++){
        float l0 = acc[r][0] + bb0;
        float l1 = acc[r][1] + bb1;
        float l2 = has2 ? (acc[r][2] + bb2) : -3.4e38f;
        float m  = wmaxf(fmaxf(l0, fmaxf(l1, l2)));
        float e0 = expf(l0 - m), e1 = expf(l1 - m);
        float e2 = has2 ? expf(l2 - m) : 0.f;
        float s  = wsumf(e0 + e1 + e2);
        int row  = row0 + ty*8 + r;
        float p0 = e0 / s, p1 = e1 / s;
        // cols: tx, tx+32, (tx<16 -> tx+64; tx==16 -> col 80 = background, dropped)
        {
            int idx = row*KCLS + tx;
            g_probs[idx] = p0;
            if (p0 > SCORE_T){
                unsigned u = __float_as_uint(p0);
                atomicAdd(&g_hist1[u>>16], 1);
                int pos = atomicAdd(&d_nCand, 1);
                g_cand[pos] = ((unsigned long long)u << 32) | (unsigned)idx;
            }
        }
        {
            int idx = row*KCLS + tx + 32;
            g_probs[idx] = p1;
            if (p1 > SCORE_T){
                unsigned u = __float_as_uint(p1);
                atomicAdd(&g_hist1[u>>16], 1);
                int pos = atomicAdd(&d_nCand, 1);
                g_cand[pos] = ((unsigned long long)u << 32) | (unsigned)idx;
            }
        }
        if (tx < 16){
            float p2 = e2 / s;
            int idx = row*KCLS + tx + 64;
            g_probs[idx] = p2;
            if (p2 > SCORE_T){
                unsigned u = __float_as_uint(p2);
                atomicAdd(&g_hist1[u>>16], 1);
                int pos = atomicAdd(&d_nCand, 1);
                g_cand[pos] = ((unsigned long long)u << 32) | (unsigned)idx;
            }
        }
    }
}

// ---------------- K2: find threshold bucket (hi 16 bits) ----------------
#define B_LO 15692   // bits(0.05f)>>16
#define B_N  565     // buckets up to bits(1.0f)>>16 = 16256
__global__ void k_bucket(){
    __shared__ int h[B_N];
    int t = threadIdx.x;
    for (int i=t; i<B_N; i+=256) h[i] = g_hist1[B_LO + i];
    __syncthreads();
    if (t==0){
        int cum=0, B=-1, nab=0;
        for (int bi=B_N-1; bi>=0; bi--){
            int c = h[bi];
            if (cum + c >= MSEL){ B = B_LO + bi; nab = cum; break; }
            cum += c;
        }
        d_B = B;
        d_nAbove = (B>=0) ? nab : cum;
        if (B < 0){ d_uCut = __float_as_uint(SCORE_T); d_r = 0; }
    }
}

// ---------------- K3: hist of low 16 bits within bucket B ----------------
__global__ void k_hist2(){
    int i = blockIdx.x*blockDim.x + threadIdx.x;
    if (i >= d_nCand) return;
    int B = d_B; if (B < 0) return;
    unsigned long long key = g_cand[i];
    unsigned u = (unsigned)(key >> 32);
    if ((int)(u >> 16) == B) atomicAdd(&g_hist2[u & 0xFFFFu], 1);
}

// ---------------- K4: exact value cutoff ----------------
__global__ void k_cut(){
    int B = d_B; if (B < 0) return;
    int t = threadIdx.x;
    __shared__ int cs[1024];
    int s = 0;
    for (int i=0;i<64;i++) s += g_hist2[t*64 + i];
    cs[t] = s;
    __syncthreads();
    if (t==0){
        int cum = d_nAbove;
        int chunk = 0;
        for (int q=1023; q>=0; q--){
            if (cum + cs[q] >= MSEL){ chunk=q; break; }
            cum += cs[q];
        }
        int low = chunk*64;
        for (int l=chunk*64+63; l>=chunk*64; l--){
            int c = g_hist2[l];
            if (cum + c >= MSEL){ low=l; break; }
            cum += c;
        }
        d_uCut = ((unsigned)B << 16) | (unsigned)low;
        d_r = MSEL - cum;            // cum = count strictly above cutoff
    }
}

// ---------------- K5: compaction ----------------
__global__ void k_compact(){
    int i = blockIdx.x*blockDim.x + threadIdx.x;
    if (i >= d_nCand) return;
    unsigned long long key = g_cand[i];
    unsigned u   = (unsigned)(key >> 32);
    unsigned idx = (unsigned)key;
    unsigned cut = d_uCut;
    if (u > cut){
        int p = atomicAdd(&d_nSel, 1);
        g_sel[p] = ((unsigned long long)(~(u | 0x80000000u)) << 32) | idx;
    } else if (u == cut){
        int p = atomicAdd(&d_nEq, 1);
        if (p < EQ_CAP) g_eq[p] = idx;
    }
}

// ---------------- K6: equals tie-break + (rare) shortfall filler ----------------
__global__ void k_eqfill(){
    __shared__ unsigned se[EQ_CAP];
    int t = threadIdx.x;
    int r = d_r;
    if (r > 0){
        int ne = min(d_nEq, EQ_CAP);
        for (int i=t; i<EQ_CAP; i+=1024) se[i] = (i<ne) ? g_eq[i] : 0xFFFFFFFFu;
        __syncthreads();
        for (int k=2;k<=EQ_CAP;k<<=1)
            for (int j=k>>1;j>0;j>>=1){
                __syncthreads();
                for (int base=0; base<EQ_CAP; base+=1024){
                    int i = base+t, l = i^j;
                    if (l > i){
                        unsigned a = se[i], bb = se[l];
                        bool asc = (i & k) == 0;
                        if ((a > bb) == asc){ se[i]=bb; se[l]=a; }
                    }
                }
            }
        __syncthreads();
        __shared__ int sbase;
        if (t==0) sbase = atomicAdd(&d_nSel, r);
        __syncthreads();
        unsigned cut = d_uCut;
        unsigned long long hi = (unsigned long long)(~(cut | 0x80000000u)) << 32;
        for (int i=t; i<r; i+=1024) g_sel[sbase+i] = hi | se[i];
    }
    __syncthreads();
    __shared__ int scnt;
    if (t==0) scnt = d_nSel;
    __syncthreads();
    if (scnt >= MSEL){ if (t==0) d_nSel = MSEL; return; }
    // shortfall: fill with smallest flat indices not above threshold (value -1.0 ties)
    __shared__ int wtot[32];
    int lane = t & 31, wd = t >> 5;
    for (int base=0; base<NFLAT; base+=1024){
        int i = base + t;
        bool f = (i < NFLAT) && !(g_probs[i] > SCORE_T);
        unsigned bal = __ballot_sync(0xffffffffu, f);
        if (lane==0) wtot[wd] = __popc(bal);
        __syncthreads();
        int off = scnt;
        for (int w2=0; w2<wd; w2++) off += wtot[w2];
        int slot = off + __popc(bal & ((1u<<lane)-1u));
        if (f && slot < MSEL)
            g_sel[slot] = ((unsigned long long)0xBF800000u << 32) | (unsigned)i;
        __syncthreads();
        if (t==0){ int tt=0; for (int w2=0;w2<32;w2++) tt+=wtot[w2]; scnt += tt; }
        __syncthreads();
        if (scnt >= MSEL) break;
    }
    if (t==0) d_nSel = MSEL;
}

// ---------------- K7: bitonic sort 2048 keys (score desc, idx asc) ----------------
__global__ void k_sort(){
    __shared__ unsigned long long s[MSEL];
    int t = threadIdx.x;
    for (int i=t; i<MSEL; i+=1024) s[i] = g_sel[i];
    for (int k=2;k<=MSEL;k<<=1)
        for (int j=k>>1;j>0;j>>=1){
            __syncthreads();
            for (int base=0; base<MSEL; base+=1024){
                int i = base+t, l = i^j;
                if (l > i){
                    unsigned long long a = s[i], bb = s[l];
                    bool asc = (i & k) == 0;
                    if ((a > bb) == asc){ s[i]=bb; s[l]=a; }
                }
            }
        }
    __syncthreads();
    for (int i=t; i<MSEL; i+=1024) g_sel[i] = s[i];
}

// ---------------- K8: per-candidate bbox dot + decode + clip + offset ----------------
__global__ __launch_bounds__(128) void k_decode(
    const float* __restrict__ x, const float* __restrict__ bw,
    const float* __restrict__ bb, const float* __restrict__ prop)
{
    int rank = blockIdx.x;
    int t = threadIdx.x;
    unsigned long long key = g_sel[rank];
    unsigned idx = (unsigned)key;
    int row = (int)(idx / KCLS);
    int cls = (int)(idx - (unsigned)row*KCLS);
    int c4 = cls*4;
    const float* xr = x + (size_t)row*DDIM;
    float a0=0.f,a1=0.f,a2=0.f,a3=0.f;
    for (int k=t; k<DDIM; k+=128){
        float xv = xr[k];
        float4 wv = *(const float4*)(bw + (size_t)k*(KCLS*4) + c4);
        a0 = fmaf(xv, wv.x, a0);
        a1 = fmaf(xv, wv.y, a1);
        a2 = fmaf(xv, wv.z, a2);
        a3 = fmaf(xv, wv.w, a3);
    }
    #pragma unroll
    for (int o=16;o;o>>=1){
        a0 += __shfl_down_sync(0xffffffffu, a0, o);
        a1 += __shfl_down_sync(0xffffffffu, a1, o);
        a2 += __shfl_down_sync(0xffffffffu, a2, o);
        a3 += __shfl_down_sync(0xffffffffu, a3, o);
    }
    __shared__ float red[4][4];
    if ((t & 31) == 0){ int w=t>>5; red[w][0]=a0; red[w][1]=a1; red[w][2]=a2; red[w][3]=a3; }
    __syncthreads();
    if (t == 0){
        float d0 = bb[c4+0] + red[0][0]+red[1][0]+red[2][0]+red[3][0];
        float d1 = bb[c4+1] + red[0][1]+red[1][1]+red[2][1]+red[3][1];
        float d2 = bb[c4+2] + red[0][2]+red[1][2]+red[2][2]+red[3][2];
        float d3 = bb[c4+3] + red[0][3]+red[1][3]+red[2][3]+red[3][3];
        float px1 = prop[row*4+0], py1 = prop[row*4+1];
        float px2 = prop[row*4+2], py2 = prop[row*4+3];
        float w  = px2 - px1, h = py2 - py1;
        float cx = px1 + 0.5f*w, cy = py1 + 0.5f*h;
        float dx = d0 / 10.0f, dy = d1 / 10.0f;
        float dw = fminf(d2 / 5.0f, SCALE_CLAMP);
        float dh = fminf(d3 / 5.0f, SCALE_CLAMP);
        float pcx = dx*w + cx, pcy = dy*h + cy;
        float pw = expf(dw)*w, ph = expf(dh)*h;
        float x1 = pcx - 0.5f*pw, y1 = pcy - 0.5f*ph;
        float x2 = pcx + 0.5f*pw, y2 = pcy + 0.5f*ph;
        x1 = fminf(fmaxf(x1, 0.f), IMG_W);
        x2 = fminf(fmaxf(x2, 0.f), IMG_W);
        y1 = fminf(fmaxf(y1, 0.f), IMG_H);
        y2 = fminf(fmaxf(y2, 0.f), IMG_H);
        g_boxes[rank*4+0]=x1; g_boxes[rank*4+1]=y1;
        g_boxes[rank*4+2]=x2; g_boxes[rank*4+3]=y2;
        float off = (float)cls * MAX_COORD;
        g_obox[rank*4+0]=x1+off; g_obox[rank*4+1]=y1+off;
        g_obox[rank*4+2]=x2+off; g_obox[rank*4+3]=y2+off;
        g_cls[rank] = cls;
        float p = g_probs[idx];
        bool v = p > SCORE_T;
        g_score[rank] = v ? p : -1.0f;
        g_valid[rank] = v ? 1 : 0;
    }
}

// ---------------- K9: per-class greedy NMS (80 blocks) ----------------
__global__ __launch_bounds__(256) void k_nms(){
    const int c = blockIdx.x;
    const int t = threadIdx.x;
    __shared__ float4 sb[MSEL];
    __shared__ short srk[MSEL];
    __shared__ unsigned char ssup[MSEL];
    __shared__ int s_n;
    __shared__ int wcnt[8];
    if (t==0) s_n = 0;
    __syncthreads();
    int lane = t & 31, wd = t >> 5;
    for (int base=0; base<MSEL; base+=256){
        int i = base + t;
        bool f = g_valid[i] && (g_cls[i] == c);
        unsigned bal = __ballot_sync(0xffffffffu, f);
        if (lane==0) wcnt[wd] = __popc(bal);
        __syncthreads();
        int off = s_n;
        for (int w2=0; w2<wd; w2++) off += wcnt[w2];
        if (f){
            int pos = off + __popc(bal & ((1u<<lane)-1u));
            sb[pos]  = *(const float4*)&g_obox[i*4];
            srk[pos] = (short)i;
            ssup[pos]= 0;
        }
        __syncthreads();
        if (t==0){ int tt=0; for (int w2=0;w2<8;w2++) tt+=wcnt[w2]; s_n += tt; }
        __syncthreads();
    }
    const int n = s_n;
    for (int k=0; k<n; k++){
        __syncthreads();
        if (ssup[k]) continue;                 // uniform
        float4 bk = sb[k];
        float ak = (bk.z - bk.x) * (bk.w - bk.y);
        for (int j=k+1+t; j<n; j+=256){
            if (ssup[j]) continue;
            float4 bj = sb[j];
            float xx1 = fmaxf(bk.x, bj.x), yy1 = fmaxf(bk.y, bj.y);
            float xx2 = fminf(bk.z, bj.z), yy2 = fminf(bk.w, bj.w);
            float inter = fmaxf(xx2-xx1, 0.f) * fmaxf(yy2-yy1, 0.f);
            float aj = (bj.z - bj.x) * (bj.w - bj.y);
            float un = fmaxf(ak + aj - inter, 1e-9f);
            if (inter / un > 0.5f) ssup[j] = 1;
        }
    }
    __syncthreads();
    for (int j=t; j<n; j+=256) if (ssup[j]) g_sup[srk[j]] = 1;
}

// ---------------- K10: final top-100 scan + output ----------------
__device__ __forceinline__ void emit_out(int i, int keep, int pk, int nK, float* out){
    int slot = keep ? pk : (nK + (i - pk));
    if (slot < TOPK){
        out[slot*4+0] = g_boxes[i*4+0];
        out[slot*4+1] = g_boxes[i*4+1];
        out[slot*4+2] = g_boxes[i*4+2];
        out[slot*4+3] = g_boxes[i*4+3];
        out[400+slot] = keep ? g_score[i] : -1.0f;
        out[500+slot] = (float)g_cls[i];
        out[600+slot] = keep ? 1.0f : 0.0f;
    }
}
__global__ void k_out(float* out){
    int t = threadIdx.x;
    __shared__ int warpS[32];
    __shared__ int s_tot;
    int i0 = 2*t, i1 = 2*t+1;
    int k0 = (g_valid[i0] && !g_sup[i0]) ? 1 : 0;
    int k1 = (g_valid[i1] && !g_sup[i1]) ? 1 : 0;
    int ps = k0 + k1;
    int lane = t & 31, wd = t >> 5;
    int v = ps;
    #pragma unroll
    for (int o=1;o<32;o<<=1){ int nn = __shfl_up_sync(0xffffffffu, v, o); if (lane>=o) v += nn; }
    if (lane==31) warpS[wd] = v;
    __syncthreads();
    if (wd==0){
        int w = warpS[lane];
        #pragma unroll
        for (int o=1;o<32;o<<=1){ int nn = __shfl_up_sync(0xffffffffu, w, o); if (lane>=o) w += nn; }
        warpS[lane] = w;
        if (lane==31) s_tot = w;
    }
    __syncthreads();
    int incl = v + ((wd>0) ? warpS[wd-1] : 0);
    int ex0 = incl - ps;          // exclusive keep-prefix at i0
    int nK = s_tot;
    emit_out(i0, k0, ex0, nK, out);
    emit_out(i1, k1, ex0 + k0, nK, out);
}

// ---------------- launch ----------------
extern "C" void kernel_launch(void* const* d_in, const int* in_sizes, int n_in,
                              void* d_out, int out_size){
    const float* x    = (const float*)d_in[0];
    const float* clsw = (const float*)d_in[1];
    const float* clsb = (const float*)d_in[2];
    const float* bw   = (const float*)d_in[3];
    const float* bbias= (const float*)d_in[4];
    const float* prop = (const float*)d_in[5];
    float* out = (float*)d_out;

    k_reset<<<256, 256>>>(out, out_size);
    k_gemm_softmax<<<NROWS/64, 256>>>(x, clsw, clsb);
    k_bucket<<<1, 256>>>();
    k_hist2<<<NFLAT/256, 256>>>();
    k_cut<<<1, 1024>>>();
    k_compact<<<NFLAT/256, 256>>>();
    k_eqfill<<<1, 1024>>>();
    k_sort<<<1, 1024>>>();
    k_decode<<<MSEL, 128>>>(x, bw, bbias, prop);
    k_nms<<<KCLS, 256>>>();
    k_out<<<1, 1024>>>(out);
}

// round 3
// speedup vs baseline: 1.4392x; 1.4392x over previous
#include <cuda_runtime.h>
#include <cuda_bf16.h>
#include <cstdint>

#define NROWS 8192
#define DDIM  1024
#define KCLS  80
#define C81   81
#define MSEL  2048
#define TOPK  100
#define NFLAT (NROWS*KCLS)
#define SCORE_T 0.05f
#define SCALE_CLAMP 4.135166556742356f
#define IMG_W 1216.0f
#define IMG_H 800.0f
#define MAX_COORD 1217.0f
#define EQ_CAP 4096

// ---------------- scratch (static __device__: no allocations) ----------------
__device__ float              g_probs[NFLAT];
__device__ unsigned long long g_cand[NFLAT];
__device__ int                g_hist1[65536];
__device__ int                g_hist2[65536];
__device__ unsigned long long g_sel[MSEL];
__device__ unsigned           g_eq[EQ_CAP];
__device__ float              g_boxes[MSEL*4];
__device__ float              g_obox[MSEL*4];
__device__ float              g_score[MSEL];
__device__ int                g_cls[MSEL];
__device__ unsigned char      g_sup[MSEL];
__device__ unsigned char      g_valid[MSEL];
__device__ int d_nCand, d_B, d_nAbove, d_r, d_nEq, d_nSel;
__device__ unsigned d_uCut;

// ---------------- helpers ----------------
__device__ __forceinline__ float wmaxf(float v){
    #pragma unroll
    for (int o=16;o;o>>=1) v = fmaxf(v, __shfl_xor_sync(0xffffffffu, v, o));
    return v;
}
__device__ __forceinline__ float wsumf(float v){
    #pragma unroll
    for (int o=16;o;o>>=1) v += __shfl_xor_sync(0xffffffffu, v, o);
    return v;
}
__device__ __forceinline__ float lo32(unsigned long long v){ return __uint_as_float((unsigned)v); }
__device__ __forceinline__ float hi32(unsigned long long v){ return __uint_as_float((unsigned)(v>>32)); }

// warp-aggregated candidate append. pred may differ per lane; all lanes call.
__device__ __forceinline__ void append_cand(bool pred, float p, int idx){
    unsigned bal = __ballot_sync(0xffffffffu, pred);
    if (!bal) return;
    int lane = threadIdx.x & 31;
    int leader = __ffs(bal) - 1;
    int base = 0;
    if (lane == leader) base = atomicAdd(&d_nCand, __popc(bal));
    base = __shfl_sync(0xffffffffu, base, leader);
    if (pred){
        unsigned u = __float_as_uint(p);
        atomicAdd(&g_hist1[u>>16], 1);
        int pos = base + __popc(bal & ((1u<<lane)-1u));
        g_cand[pos] = ((unsigned long long)u << 32) | (unsigned)idx;
    }
}

// ---------------- K0: reset ----------------
__global__ void k_reset(float* out, int out_size){
    int i = blockIdx.x*blockDim.x + threadIdx.x;
    if (i < 65536){ g_hist1[i]=0; g_hist2[i]=0; }
    if (i < MSEL)  g_sup[i]=0;
    if (i < out_size) out[i]=0.0f;
    if (i == 0){ d_nCand=0; d_nSel=0; d_nEq=0; d_r=0; d_B=-2; d_nAbove=0; d_uCut=0; }
}

// ---------------- K1: cls GEMM (packed f32x2) + softmax + candidate append ----------------
// block 256 thr (8 warps). tile 64 rows x 81 cols, k-chunk 32.
// warp ty owns rows ty*8..ty*8+7 as 4 packed row-pairs; lane tx owns cols {tx, tx+32, tx+64}.
__global__ __launch_bounds__(256) void k_gemm_softmax(
    const float* __restrict__ x, const float* __restrict__ w, const float* __restrict__ b)
{
    __shared__ __align__(16) float xsT[32][66];   // k-major: [k][row], stride 66 (8B-aligned, 2-way STS ok)
    __shared__ float ws[32][81];
    const int tid = threadIdx.x;
    const int ty = tid >> 5, tx = tid & 31;
    const int row0 = blockIdx.x * 64;
    const bool has2 = (tx < 17);

    unsigned long long acc[4][3] = {};  // packed fp32 pairs (rows 2p, 2p+1)

    float rx[8]; float rw[11];
    // prologue: prefetch chunk 0 into registers
    {
        const float* xp = x + (size_t)row0 * DDIM;
        #pragma unroll
        for (int i=0;i<8;i++){ int e=tid+i*256; int r=e>>5, k=e&31; rx[i]=xp[(size_t)r*DDIM+k]; }
        #pragma unroll
        for (int i=0;i<11;i++){ int e=tid+i*256; if (e<32*81){ int k=e/81, c=e-k*81; rw[i]=w[(size_t)k*C81+c]; } }
    }

    for (int kc=0; kc<DDIM; kc+=32){
        // stage registers -> smem
        #pragma unroll
        for (int i=0;i<8;i++){ int e=tid+i*256; int r=e>>5, k=e&31; xsT[k][r]=rx[i]; }
        #pragma unroll
        for (int i=0;i<11;i++){ int e=tid+i*256; if (e<32*81){ int k=e/81, c=e-k*81; ws[k][c]=rw[i]; } }
        __syncthreads();
        // prefetch next chunk (latency hidden by compute below)
        if (kc + 32 < DDIM){
            const float* xp = x + (size_t)row0*DDIM + kc + 32;
            const float* wp = w + (size_t)(kc+32)*C81;
            #pragma unroll
            for (int i=0;i<8;i++){ int e=tid+i*256; int r=e>>5, k=e&31; rx[i]=xp[(size_t)r*DDIM+k]; }
            #pragma unroll
            for (int i=0;i<11;i++){ int e=tid+i*256; if (e<32*81){ int k=e/81, c=e-k*81; rw[i]=wp[(size_t)k*C81+c]; } }
        }
        // compute
        #pragma unroll
        for (int k=0;k<32;k++){
            float b0 = ws[k][tx];
            float b1 = ws[k][tx+32];
            float b2 = has2 ? ws[k][tx+64] : 0.f;
            unsigned long long b0d, b1d, b2d;
            asm("mov.b64 %0,{%1,%1};" : "=l"(b0d) : "f"(b0));
            asm("mov.b64 %0,{%1,%1};" : "=l"(b1d) : "f"(b1));
            asm("mov.b64 %0,{%1,%1};" : "=l"(b2d) : "f"(b2));
            #pragma unroll
            for (int p=0;p<4;p++){
                unsigned long long a = *(const unsigned long long*)&xsT[k][ty*8 + 2*p];
                asm("fma.rn.f32x2 %0,%1,%2,%0;" : "+l"(acc[p][0]) : "l"(a), "l"(b0d));
                asm("fma.rn.f32x2 %0,%1,%2,%0;" : "+l"(acc[p][1]) : "l"(a), "l"(b1d));
                asm("fma.rn.f32x2 %0,%1,%2,%0;" : "+l"(acc[p][2]) : "l"(a), "l"(b2d));
            }
        }
        __syncthreads();
    }

    const float bb0 = b[tx], bb1 = b[tx+32];
    const float bb2 = has2 ? b[tx+64] : 0.f;

    #pragma unroll
    for (int p=0;p<4;p++){
        #pragma unroll
        for (int h=0;h<2;h++){
            float l0 = (h ? hi32(acc[p][0]) : lo32(acc[p][0])) + bb0;
            float l1 = (h ? hi32(acc[p][1]) : lo32(acc[p][1])) + bb1;
            float l2 = has2 ? ((h ? hi32(acc[p][2]) : lo32(acc[p][2])) + bb2) : -3.4e38f;
            float m  = wmaxf(fmaxf(l0, fmaxf(l1, l2)));
            float e0 = expf(l0 - m), e1 = expf(l1 - m);
            float e2 = has2 ? expf(l2 - m) : 0.f;
            float s  = wsumf(e0 + e1 + e2);
            int row  = row0 + ty*8 + 2*p + h;
            float p0 = e0 / s, p1 = e1 / s;
            {
                int idx = row*KCLS + tx;
                g_probs[idx] = p0;
                append_cand(p0 > SCORE_T, p0, idx);
            }
            {
                int idx = row*KCLS + tx + 32;
                g_probs[idx] = p1;
                append_cand(p1 > SCORE_T, p1, idx);
            }
            {
                float p2 = (tx < 16) ? (e2 / s) : 0.f;    // tx==16 is background col 80: dropped
                int idx = row*KCLS + tx + 64;
                if (tx < 16) g_probs[idx] = p2;
                append_cand((tx < 16) && (p2 > SCORE_T), p2, idx);
            }
        }
    }
}

// ---------------- K2: find threshold bucket (hi 16 bits) ----------------
#define B_LO 15692
#define B_N  565
__global__ void k_bucket(){
    __shared__ int h[B_N];
    int t = threadIdx.x;
    for (int i=t; i<B_N; i+=256) h[i] = g_hist1[B_LO + i];
    __syncthreads();
    if (t==0){
        int cum=0, B=-1, nab=0;
        for (int bi=B_N-1; bi>=0; bi--){
            int c = h[bi];
            if (cum + c >= MSEL){ B = B_LO + bi; nab = cum; break; }
            cum += c;
        }
        d_B = B;
        d_nAbove = (B>=0) ? nab : cum;
        if (B < 0){ d_uCut = __float_as_uint(SCORE_T); d_r = 0; }
    }
}

// ---------------- K3: hist of low 16 bits within bucket B (grid-stride) ----------------
__global__ void k_hist2(){
    int B = d_B; if (B < 0) return;
    int n = d_nCand;
    for (int i = blockIdx.x*blockDim.x + threadIdx.x; i < n; i += gridDim.x*blockDim.x){
        unsigned u = (unsigned)(g_cand[i] >> 32);
        if ((int)(u >> 16) == B) atomicAdd(&g_hist2[u & 0xFFFFu], 1);
    }
}

// ---------------- K4: exact value cutoff ----------------
__global__ void k_cut(){
    if (d_B < 0) return;
    __shared__ int cs[1024];
    __shared__ int gs[32];
    int t = threadIdx.x;
    int s = 0;
    #pragma unroll 8
    for (int i=0;i<64;i++) s += g_hist2[t*64 + i];
    cs[t] = s;
    __syncthreads();
    if (t < 32){ int g=0; for (int i=0;i<32;i++) g += cs[t*32+i]; gs[t]=g; }
    __syncthreads();
    if (t==0){
        int cum = d_nAbove;
        int grp = 0;
        for (int g=31; g>=0; g--){ if (cum + gs[g] >= MSEL){ grp=g; break; } cum += gs[g]; }
        int chunk = grp*32;
        for (int q=grp*32+31; q>=grp*32; q--){ if (cum + cs[q] >= MSEL){ chunk=q; break; } cum += cs[q]; }
        int low = chunk*64;
        for (int l=chunk*64+63; l>=chunk*64; l--){ int c=g_hist2[l]; if (cum + c >= MSEL){ low=l; break; } cum += c; }
        d_uCut = ((unsigned)d_B << 16) | (unsigned)low;
        d_r = MSEL - cum;                    // cum = strictly-above count
    }
}

// ---------------- K5: compaction (grid-stride) ----------------
__global__ void k_compact(){
    int n = d_nCand;
    unsigned cut = d_uCut;
    for (int i = blockIdx.x*blockDim.x + threadIdx.x; i < n; i += gridDim.x*blockDim.x){
        unsigned long long key = g_cand[i];
        unsigned u   = (unsigned)(key >> 32);
        unsigned idx = (unsigned)key;
        if (u > cut){
            int p = atomicAdd(&d_nSel, 1);
            g_sel[p] = ((unsigned long long)(~(u | 0x80000000u)) << 32) | idx;
        } else if (u == cut){
            int p = atomicAdd(&d_nEq, 1);
            if (p < EQ_CAP) g_eq[p] = idx;
        }
    }
}

// ---------------- K6: tie-break (dynamic-size) + shortfall + bitonic sort of 2048 ----------------
__global__ void k_sortsel(){
    __shared__ unsigned se[EQ_CAP];
    __shared__ unsigned long long s[MSEL];
    __shared__ int sb_;
    int t = threadIdx.x;
    int r = d_r;
    if (r > 0){
        int ne = min(d_nEq, EQ_CAP);
        int np = 1; while (np < ne) np <<= 1;
        for (int i=t; i<np; i+=1024) se[i] = (i<ne) ? g_eq[i] : 0xFFFFFFFFu;
        __syncthreads();
        for (int k=2;k<=np;k<<=1)
            for (int j=k>>1;j>0;j>>=1){
                for (int base=0; base<np; base+=1024){
                    int i = base+t;
                    if (i < np){
                        int l = i^j;
                        if (l > i && l < np){
                            unsigned a = se[i], bb = se[l];
                            bool asc = (i & k) == 0;
                            if ((a > bb) == asc){ se[i]=bb; se[l]=a; }
                        }
                    }
                }
                __syncthreads();
            }
        if (t==0) sb_ = atomicAdd(&d_nSel, r);
        __syncthreads();
        unsigned cut = d_uCut;
        unsigned long long hi = (unsigned long long)(~(cut | 0x80000000u)) << 32;
        for (int i=t; i<r; i+=1024) g_sel[sb_+i] = hi | se[i];
        __syncthreads();
    }
    // shortfall (fewer than MSEL candidates above threshold) — rarely taken
    __shared__ int scnt;
    __shared__ int wtot[32];
    if (t==0) scnt = d_nSel;
    __syncthreads();
    if (scnt < MSEL){
        int lane = t & 31, wd = t >> 5;
        for (int base=0; base<NFLAT; base+=1024){
            int i = base + t;
            bool f = (i < NFLAT) && !(g_probs[i] > SCORE_T);
            unsigned bal = __ballot_sync(0xffffffffu, f);
            if (lane==0) wtot[wd] = __popc(bal);
            __syncthreads();
            int off = scnt;
            for (int w2=0; w2<wd; w2++) off += wtot[w2];
            int slot = off + __popc(bal & ((1u<<lane)-1u));
            if (f && slot < MSEL)
                g_sel[slot] = ((unsigned long long)0xBF800000u << 32) | (unsigned)i;
            __syncthreads();
            if (t==0){ int tt=0; for (int w2=0;w2<32;w2++) tt+=wtot[w2]; scnt += tt; }
            __syncthreads();
            if (scnt >= MSEL) break;
        }
    }
    __syncthreads();
    // bitonic sort of the 2048 selected keys (score desc, idx asc)
    for (int i=t; i<MSEL; i+=1024) s[i] = g_sel[i];
    for (int k=2;k<=MSEL;k<<=1)
        for (int j=k>>1;j>0;j>>=1){
            __syncthreads();
            #pragma unroll
            for (int base=0; base<MSEL; base+=1024){
                int i = base+t, l = i^j;
                if (l > i){
                    unsigned long long a = s[i], bb = s[l];
                    bool asc = (i & k) == 0;
                    if ((a > bb) == asc){ s[i]=bb; s[l]=a; }
                }
            }
        }
    __syncthreads();
    for (int i=t; i<MSEL; i+=1024) g_sel[i] = s[i];
}

// ---------------- K7: per-candidate bbox dot + decode + clip + offset ----------------
__global__ __launch_bounds__(128) void k_decode(
    const float* __restrict__ x, const float* __restrict__ bw,
    const float* __restrict__ bb, const float* __restrict__ prop)
{
    int rank = blockIdx.x;
    int t = threadIdx.x;
    unsigned long long key = g_sel[rank];
    unsigned idx = (unsigned)key;
    int row = (int)(idx / KCLS);
    int cls = (int)(idx - (unsigned)row*KCLS);
    int c4 = cls*4;
    const float* xr = x + (size_t)row*DDIM;
    float a0=0.f,a1=0.f,a2=0.f,a3=0.f;
    for (int k=t; k<DDIM; k+=128){
        float xv = xr[k];
        float4 wv = *(const float4*)(bw + (size_t)k*(KCLS*4) + c4);
        a0 = fmaf(xv, wv.x, a0);
        a1 = fmaf(xv, wv.y, a1);
        a2 = fmaf(xv, wv.z, a2);
        a3 = fmaf(xv, wv.w, a3);
    }
    #pragma unroll
    for (int o=16;o;o>>=1){
        a0 += __shfl_down_sync(0xffffffffu, a0, o);
        a1 += __shfl_down_sync(0xffffffffu, a1, o);
        a2 += __shfl_down_sync(0xffffffffu, a2, o);
        a3 += __shfl_down_sync(0xffffffffu, a3, o);
    }
    __shared__ float red[4][4];
    if ((t & 31) == 0){ int w=t>>5; red[w][0]=a0; red[w][1]=a1; red[w][2]=a2; red[w][3]=a3; }
    __syncthreads();
    if (t == 0){
        float d0 = bb[c4+0] + red[0][0]+red[1][0]+red[2][0]+red[3][0];
        float d1 = bb[c4+1] + red[0][1]+red[1][1]+red[2][1]+red[3][1];
        float d2 = bb[c4+2] + red[0][2]+red[1][2]+red[2][2]+red[3][2];
        float d3 = bb[c4+3] + red[0][3]+red[1][3]+red[2][3]+red[3][3];
        float px1 = prop[row*4+0], py1 = prop[row*4+1];
        float px2 = prop[row*4+2], py2 = prop[row*4+3];
        float w  = px2 - px1, h = py2 - py1;
        float cx = px1 + 0.5f*w, cy = py1 + 0.5f*h;
        float dx = d0 / 10.0f, dy = d1 / 10.0f;
        float dw = fminf(d2 / 5.0f, SCALE_CLAMP);
        float dh = fminf(d3 / 5.0f, SCALE_CLAMP);
        float pcx = dx*w + cx, pcy = dy*h + cy;
        float pw = expf(dw)*w, ph = expf(dh)*h;
        float x1 = pcx - 0.5f*pw, y1 = pcy - 0.5f*ph;
        float x2 = pcx + 0.5f*pw, y2 = pcy + 0.5f*ph;
        x1 = fminf(fmaxf(x1, 0.f), IMG_W);
        x2 = fminf(fmaxf(x2, 0.f), IMG_W);
        y1 = fminf(fmaxf(y1, 0.f), IMG_H);
        y2 = fminf(fmaxf(y2, 0.f), IMG_H);
        g_boxes[rank*4+0]=x1; g_boxes[rank*4+1]=y1;
        g_boxes[rank*4+2]=x2; g_boxes[rank*4+3]=y2;
        float off = (float)cls * MAX_COORD;
        g_obox[rank*4+0]=x1+off; g_obox[rank*4+1]=y1+off;
        g_obox[rank*4+2]=x2+off; g_obox[rank*4+3]=y2+off;
        g_cls[rank] = cls;
        float p = g_probs[idx];
        bool v = p > SCORE_T;
        g_score[rank] = v ? p : -1.0f;
        g_valid[rank] = v ? 1 : 0;
    }
}

// ---------------- K8: per-class greedy NMS (80 blocks) ----------------
__global__ __launch_bounds__(256) void k_nms(){
    const int c = blockIdx.x;
    const int t = threadIdx.x;
    __shared__ float4 sb[MSEL];
    __shared__ short srk[MSEL];
    __shared__ unsigned char ssup[MSEL];
    __shared__ int s_n;
    __shared__ int wcnt[8];
    if (t==0) s_n = 0;
    __syncthreads();
    int lane = t & 31, wd = t >> 5;
    for (int base=0; base<MSEL; base+=256){
        int i = base + t;
        bool f = g_valid[i] && (g_cls[i] == c);
        unsigned bal = __ballot_sync(0xffffffffu, f);
        if (lane==0) wcnt[wd] = __popc(bal);
        __syncthreads();
        int off = s_n;
        for (int w2=0; w2<wd; w2++) off += wcnt[w2];
        if (f){
            int pos = off + __popc(bal & ((1u<<lane)-1u));
            sb[pos]  = *(const float4*)&g_obox[i*4];
            srk[pos] = (short)i;
            ssup[pos]= 0;
        }
        __syncthreads();
        if (t==0){ int tt=0; for (int w2=0;w2<8;w2++) tt+=wcnt[w2]; s_n += tt; }
        __syncthreads();
    }
    const int n = s_n;
    for (int k=0; k<n; k++){
        __syncthreads();
        if (ssup[k]) continue;
        float4 bk = sb[k];
        float ak = (bk.z - bk.x) * (bk.w - bk.y);
        for (int j=k+1+t; j<n; j+=256){
            if (ssup[j]) continue;
            float4 bj = sb[j];
            float xx1 = fmaxf(bk.x, bj.x), yy1 = fmaxf(bk.y, bj.y);
            float xx2 = fminf(bk.z, bj.z), yy2 = fminf(bk.w, bj.w);
            float inter = fmaxf(xx2-xx1, 0.f) * fmaxf(yy2-yy1, 0.f);
            float aj = (bj.z - bj.x) * (bj.w - bj.y);
            float un = fmaxf(ak + aj - inter, 1e-9f);
            if (inter / un > 0.5f) ssup[j] = 1;
        }
    }
    __syncthreads();
    for (int j=t; j<n; j+=256) if (ssup[j]) g_sup[srk[j]] = 1;
}

// ---------------- K9: final top-100 scan + output ----------------
__device__ __forceinline__ void emit_out(int i, int keep, int pk, int nK, float* out){
    int slot = keep ? pk : (nK + (i - pk));
    if (slot < TOPK){
        out[slot*4+0] = g_boxes[i*4+0];
        out[slot*4+1] = g_boxes[i*4+1];
        out[slot*4+2] = g_boxes[i*4+2];
        out[slot*4+3] = g_boxes[i*4+3];
        out[400+slot] = keep ? g_score[i] : -1.0f;
        out[500+slot] = (float)g_cls[i];
        out[600+slot] = keep ? 1.0f : 0.0f;
    }
}
__global__ void k_out(float* out){
    int t = threadIdx.x;
    __shared__ int warpS[32];
    __shared__ int s_tot;
    int i0 = 2*t, i1 = 2*t+1;
    int k0 = (g_valid[i0] && !g_sup[i0]) ? 1 : 0;
    int k1 = (g_valid[i1] && !g_sup[i1]) ? 1 : 0;
    int ps = k0 + k1;
    int lane = t & 31, wd = t >> 5;
    int v = ps;
    #pragma unroll
    for (int o=1;o<32;o<<=1){ int nn = __shfl_up_sync(0xffffffffu, v, o); if (lane>=o) v += nn; }
    if (lane==31) warpS[wd] = v;
    __syncthreads();
    if (wd==0){
        int w = warpS[lane];
        #pragma unroll
        for (int o=1;o<32;o<<=1){ int nn = __shfl_up_sync(0xffffffffu, w, o); if (lane>=o) w += nn; }
        warpS[lane] = w;
        if (lane==31) s_tot = w;
    }
    __syncthreads();
    int incl = v + ((wd>0) ? warpS[wd-1] : 0);
    int ex0 = incl - ps;
    int nK = s_tot;
    emit_out(i0, k0, ex0, nK, out);
    emit_out(i1, k1, ex0 + k0, nK, out);
}

// ---------------- launch ----------------
extern "C" void kernel_launch(void* const* d_in, const int* in_sizes, int n_in,
                              void* d_out, int out_size){
    const float* x    = (const float*)d_in[0];
    const float* clsw = (const float*)d_in[1];
    const float* clsb = (const float*)d_in[2];
    const float* bw   = (const float*)d_in[3];
    const float* bbias= (const float*)d_in[4];
    const float* prop = (const float*)d_in[5];
    float* out = (float*)d_out;

    k_reset<<<256, 256>>>(out, out_size);
    k_gemm_softmax<<<NROWS/64, 256>>>(x, clsw, clsb);
    k_bucket<<<1, 256>>>();
    k_hist2<<<256, 256>>>();
    k_cut<<<1, 1024>>>();
    k_compact<<<256, 256>>>();
    k_sortsel<<<1, 1024>>>();
    k_decode<<<MSEL, 128>>>(x, bw, bbias, prop);
    k_nms<<<KCLS, 256>>>();
    k_out<<<1, 1024>>>(out);
}

// round 4
// speedup vs baseline: 1.6881x; 1.1729x over previous
#include <cuda_runtime.h>
#include <cuda_bf16.h>
#include <cstdint>

#define NROWS 8192
#define DDIM  1024
#define KCLS  80
#define C81   81
#define MSEL  2048
#define TOPK  100
#define NFLAT (NROWS*KCLS)
#define SCORE_T 0.05f
#define SCALE_CLAMP 4.135166556742356f
#define IMG_W 1216.0f
#define IMG_H 800.0f
#define MAX_COORD 1217.0f
#define EQ_CAP 4096
#define B_LO 15692          // bits(0.05f)>>16
#define B_N  565            // buckets up to bits(1.0f)>>16 inclusive

// ---------------- scratch (static __device__: no allocations) ----------------
__device__ float              g_probs[NFLAT];
__device__ unsigned long long g_cand[NFLAT];
__device__ int                g_hist1[B_N];
__device__ unsigned long long g_sel[MSEL];
__device__ float4             g_bwT[KCLS*DDIM];       // [cls][k] -> 4 deltas
__device__ float              g_boxes[MSEL*4];
__device__ float              g_obox[MSEL*4];
__device__ float              g_score[MSEL];
__device__ int                g_cls[MSEL];
__device__ unsigned char      g_sup[MSEL];
__device__ unsigned char      g_valid[MSEL];
__device__ int d_nCand;

// ---------------- helpers ----------------
__device__ __forceinline__ float wmaxf(float v){
    #pragma unroll
    for (int o=16;o;o>>=1) v = fmaxf(v, __shfl_xor_sync(0xffffffffu, v, o));
    return v;
}
__device__ __forceinline__ float wsumf(float v){
    #pragma unroll
    for (int o=16;o;o>>=1) v += __shfl_xor_sync(0xffffffffu, v, o);
    return v;
}
__device__ __forceinline__ float lo32(unsigned long long v){ return __uint_as_float((unsigned)v); }
__device__ __forceinline__ float hi32(unsigned long long v){ return __uint_as_float((unsigned)(v>>32)); }

__device__ __forceinline__ void append_cand(bool pred, float p, int idx){
    unsigned bal = __ballot_sync(0xffffffffu, pred);
    if (!bal) return;
    int lane = threadIdx.x & 31;
    int leader = __ffs(bal) - 1;
    int base = 0;
    if (lane == leader) base = atomicAdd(&d_nCand, __popc(bal));
    base = __shfl_sync(0xffffffffu, base, leader);
    if (pred){
        unsigned u = __float_as_uint(p);
        atomicAdd(&g_hist1[(int)(u>>16) - B_LO], 1);
        int pos = base + __popc(bal & ((1u<<lane)-1u));
        g_cand[pos] = ((unsigned long long)u << 32) | (unsigned)idx;
    }
}

// ---------------- K0: prep (zero state + transpose bbox weights) ----------------
__global__ void k_prep(const float* __restrict__ bw, float* out, int out_size){
    int i = blockIdx.x*blockDim.x + threadIdx.x;
    int nT = gridDim.x*blockDim.x;
    if (i < B_N)  g_hist1[i] = 0;
    if (i < MSEL) g_sup[i] = 0;
    if (i < out_size) out[i] = 0.0f;
    if (i == 0) d_nCand = 0;
    // transpose: bw float4 m = k*80+cls  ->  g_bwT[cls*1024+k]
    const float4* bw4 = (const float4*)bw;
    for (int m = i; m < KCLS*DDIM; m += nT){
        int cls = m >> 10;          // m = cls*1024 + k (write-coalesced)
        int k   = m & 1023;
        g_bwT[m] = bw4[k*KCLS + cls];
    }
}

// ---------------- K1: cls GEMM (packed f32x2) + softmax + candidate append ----------------
__global__ __launch_bounds__(256) void k_gemm_softmax(
    const float* __restrict__ x, const float* __restrict__ w, const float* __restrict__ b)
{
    __shared__ __align__(16) float xsT[32][66];
    __shared__ float ws[32][81];
    const int tid = threadIdx.x;
    const int ty = tid >> 5, tx = tid & 31;
    const int row0 = blockIdx.x * 64;
    const bool has2 = (tx < 17);

    unsigned long long acc[4][3] = {};
    float rx[8]; float rw[11];
    {
        const float* xp = x + (size_t)row0 * DDIM;
        #pragma unroll
        for (int i=0;i<8;i++){ int e=tid+i*256; int r=e>>5, k=e&31; rx[i]=xp[(size_t)r*DDIM+k]; }
        #pragma unroll
        for (int i=0;i<11;i++){ int e=tid+i*256; if (e<32*81){ int k=e/81, c=e-k*81; rw[i]=w[(size_t)k*C81+c]; } }
    }

    for (int kc=0; kc<DDIM; kc+=32){
        #pragma unroll
        for (int i=0;i<8;i++){ int e=tid+i*256; int r=e>>5, k=e&31; xsT[k][r]=rx[i]; }
        #pragma unroll
        for (int i=0;i<11;i++){ int e=tid+i*256; if (e<32*81){ int k=e/81, c=e-k*81; ws[k][c]=rw[i]; } }
        __syncthreads();
        if (kc + 32 < DDIM){
            const float* xp = x + (size_t)row0*DDIM + kc + 32;
            const float* wp = w + (size_t)(kc+32)*C81;
            #pragma unroll
            for (int i=0;i<8;i++){ int e=tid+i*256; int r=e>>5, k=e&31; rx[i]=xp[(size_t)r*DDIM+k]; }
            #pragma unroll
            for (int i=0;i<11;i++){ int e=tid+i*256; if (e<32*81){ int k=e/81, c=e-k*81; rw[i]=wp[(size_t)k*C81+c]; } }
        }
        #pragma unroll
        for (int k=0;k<32;k++){
            float b0 = ws[k][tx];
            float b1 = ws[k][tx+32];
            float b2 = has2 ? ws[k][tx+64] : 0.f;
            unsigned long long b0d, b1d, b2d;
            asm("mov.b64 %0,{%1,%1};" : "=l"(b0d) : "f"(b0));
            asm("mov.b64 %0,{%1,%1};" : "=l"(b1d) : "f"(b1));
            asm("mov.b64 %0,{%1,%1};" : "=l"(b2d) : "f"(b2));
            #pragma unroll
            for (int p=0;p<4;p++){
                unsigned long long a = *(const unsigned long long*)&xsT[k][ty*8 + 2*p];
                asm("fma.rn.f32x2 %0,%1,%2,%0;" : "+l"(acc[p][0]) : "l"(a), "l"(b0d));
                asm("fma.rn.f32x2 %0,%1,%2,%0;" : "+l"(acc[p][1]) : "l"(a), "l"(b1d));
                asm("fma.rn.f32x2 %0,%1,%2,%0;" : "+l"(acc[p][2]) : "l"(a), "l"(b2d));
            }
        }
        __syncthreads();
    }

    const float bb0 = b[tx], bb1 = b[tx+32];
    const float bb2 = has2 ? b[tx+64] : 0.f;

    #pragma unroll
    for (int p=0;p<4;p++){
        #pragma unroll
        for (int h=0;h<2;h++){
            float l0 = (h ? hi32(acc[p][0]) : lo32(acc[p][0])) + bb0;
            float l1 = (h ? hi32(acc[p][1]) : lo32(acc[p][1])) + bb1;
            float l2 = has2 ? ((h ? hi32(acc[p][2]) : lo32(acc[p][2])) + bb2) : -3.4e38f;
            float m  = wmaxf(fmaxf(l0, fmaxf(l1, l2)));
            float e0 = expf(l0 - m), e1 = expf(l1 - m);
            float e2 = has2 ? expf(l2 - m) : 0.f;
            float s  = wsumf(e0 + e1 + e2);
            int row  = row0 + ty*8 + 2*p + h;
            float p0 = e0 / s, p1 = e1 / s;
            {
                int idx = row*KCLS + tx;
                g_probs[idx] = p0;
                append_cand(p0 > SCORE_T, p0, idx);
            }
            {
                int idx = row*KCLS + tx + 32;
                g_probs[idx] = p1;
                append_cand(p1 > SCORE_T, p1, idx);
            }
            {
                float p2 = (tx < 16) ? (e2 / s) : 0.f;
                int idx = row*KCLS + tx + 64;
                if (tx < 16) g_probs[idx] = p2;
                append_cand((tx < 16) && (p2 > SCORE_T), p2, idx);
            }
        }
    }
}

// ---------------- K2: fused selection (bucket, 2x8-bit select, compact, tie-break, sort) ----------------
__global__ __launch_bounds__(1024) void k_select(){
    __shared__ unsigned long long sel[MSEL];     // 16KB
    __shared__ unsigned se[EQ_CAP];              // 16KB
    __shared__ int hist[256];
    __shared__ int hA[B_N];
    __shared__ int s_nSel, s_nEq;
    __shared__ unsigned s_cut;
    __shared__ int s_r, s_B, s_nab, s_sub;
    const int t = threadIdx.x;
    const int n = d_nCand;

    // --- stage A: find high-16 bucket B from g_hist1 ---
    for (int i=t; i<B_N; i+=1024) hA[i] = g_hist1[i];
    if (t==0){ s_nSel=0; s_nEq=0; }
    __syncthreads();
    if (t==0){
        int cum=0, B=-1, nab=0;
        for (int bi=B_N-1; bi>=0; bi--){
            int c = hA[bi];
            if (cum + c >= MSEL){ B = bi; nab = cum; break; }
            cum += c;
        }
        s_B = B; s_nab = (B>=0) ? nab : cum;
        if (B < 0){ s_cut = __float_as_uint(SCORE_T); s_r = 0; }
    }
    __syncthreads();
    const int B = s_B;

    if (B >= 0){
        const unsigned Bfull = (unsigned)(B + B_LO);
        // --- stage B: histogram bits [15:8] within bucket B ---
        for (int i=t; i<256; i+=1024) hist[i] = 0;
        __syncthreads();
        for (int i=t; i<n; i+=1024){
            unsigned u = (unsigned)(g_cand[i] >> 32);
            if ((u >> 16) == Bfull) atomicAdd(&hist[(u >> 8) & 255u], 1);
        }
        __syncthreads();
        if (t==0){
            int cum = s_nab, b1 = 0;
            for (int q=255; q>=0; q--){ int c=hist[q]; if (cum + c >= MSEL){ b1=q; break; } cum += c; }
            s_sub = b1; s_nab = cum;
        }
        __syncthreads();
        const unsigned pfx = (Bfull << 8) | (unsigned)s_sub;
        // --- stage C: histogram bits [7:0] within (B, b1) ---
        for (int i=t; i<256; i+=1024) hist[i] = 0;
        __syncthreads();
        for (int i=t; i<n; i+=1024){
            unsigned u = (unsigned)(g_cand[i] >> 32);
            if ((u >> 8) == pfx) atomicAdd(&hist[u & 255u], 1);
        }
        __syncthreads();
        if (t==0){
            int cum = s_nab, b0 = 0;
            for (int q=255; q>=0; q--){ int c=hist[q]; if (cum + c >= MSEL){ b0=q; break; } cum += c; }
            s_cut = (pfx << 8) | (unsigned)b0;
            s_r = MSEL - cum;            // cum = strictly-above-cut count
        }
        __syncthreads();
    }

    // --- stage D: compact ---
    const unsigned cut = s_cut;
    for (int i=t; i<n; i+=1024){
        unsigned long long key = g_cand[i];
        unsigned u   = (unsigned)(key >> 32);
        unsigned idx = (unsigned)key;
        if (u > cut){
            int p = atomicAdd(&s_nSel, 1);
            sel[p] = ((unsigned long long)(~(u | 0x80000000u)) << 32) | idx;
        } else if (u == cut){
            int p = atomicAdd(&s_nEq, 1);
            if (p < EQ_CAP) se[p] = idx;
        }
    }
    __syncthreads();

    // --- stage E: tie-break at cutoff (sort eq indices asc, take first r) ---
    int r = s_r;
    if (r > 0){
        int ne = min(s_nEq, EQ_CAP);
        int np = 1; while (np < ne) np <<= 1;
        for (int i=t; i<np; i+=1024) if (i >= ne) se[i] = 0xFFFFFFFFu;
        __syncthreads();
        for (int k=2;k<=np;k<<=1)
            for (int j=k>>1;j>0;j>>=1){
                for (int base=0; base<np; base+=1024){
                    int i = base+t;
                    if (i < np){
                        int l = i^j;
                        if (l > i && l < np){
                            unsigned a = se[i], bb = se[l];
                            bool asc = (i & k) == 0;
                            if ((a > bb) == asc){ se[i]=bb; se[l]=a; }
                        }
                    }
                }
                __syncthreads();
            }
        unsigned long long hi = (unsigned long long)(~(cut | 0x80000000u)) << 32;
        int base = s_nSel;
        for (int i=t; i<r; i+=1024) sel[base+i] = hi | se[i];
        __syncthreads();
        if (t==0) s_nSel += r;
        __syncthreads();
    }

    // --- stage F: shortfall fill (rare: fewer than MSEL above threshold) ---
    if (s_nSel < MSEL){
        __shared__ int wtot[32];
        __shared__ int scnt;
        if (t==0) scnt = s_nSel;
        __syncthreads();
        int lane = t & 31, wd = t >> 5;
        for (int base=0; base<NFLAT; base+=1024){
            int i = base + t;
            bool f = (i < NFLAT) && !(g_probs[i] > SCORE_T);
            unsigned bal = __ballot_sync(0xffffffffu, f);
            if (lane==0) wtot[wd] = __popc(bal);
            __syncthreads();
            int off = scnt;
            for (int w2=0; w2<wd; w2++) off += wtot[w2];
            int slot = off + __popc(bal & ((1u<<lane)-1u));
            if (f && slot < MSEL)
                sel[slot] = ((unsigned long long)0xBF800000u << 32) | (unsigned)i;
            __syncthreads();
            if (t==0){ int tt=0; for (int w2=0;w2<32;w2++) tt+=wtot[w2]; scnt += tt; }
            __syncthreads();
            if (scnt >= MSEL) break;
        }
    }
    __syncthreads();

    // --- stage G: bitonic sort 2048 (score desc, idx asc) ---
    for (int k=2;k<=MSEL;k<<=1)
        for (int j=k>>1;j>0;j>>=1){
            #pragma unroll
            for (int base=0; base<MSEL; base+=1024){
                int i = base+t, l = i^j;
                if (l > i){
                    unsigned long long a = sel[i], bb = sel[l];
                    bool asc = (i & k) == 0;
                    if ((a > bb) == asc){ sel[i]=bb; sel[l]=a; }
                }
            }
            __syncthreads();
        }
    for (int i=t; i<MSEL; i+=1024) g_sel[i] = sel[i];
}

// ---------------- K3: per-candidate bbox dot + decode + clip + offset ----------------
__global__ __launch_bounds__(128) void k_decode(
    const float* __restrict__ x, const float* __restrict__ bb, const float* __restrict__ prop)
{
    int rank = blockIdx.x;
    int t = threadIdx.x;
    unsigned long long key = g_sel[rank];
    unsigned idx = (unsigned)key;
    int row = (int)(idx / KCLS);
    int cls = (int)(idx - (unsigned)row*KCLS);
    const float* xr = x + (size_t)row*DDIM;
    const float4* wt = g_bwT + (size_t)cls*DDIM;
    float a0=0.f,a1=0.f,a2=0.f,a3=0.f;
    #pragma unroll
    for (int k=t; k<DDIM; k+=128){
        float xv = xr[k];
        float4 wv = wt[k];
        a0 = fmaf(xv, wv.x, a0);
        a1 = fmaf(xv, wv.y, a1);
        a2 = fmaf(xv, wv.z, a2);
        a3 = fmaf(xv, wv.w, a3);
    }
    #pragma unroll
    for (int o=16;o;o>>=1){
        a0 += __shfl_down_sync(0xffffffffu, a0, o);
        a1 += __shfl_down_sync(0xffffffffu, a1, o);
        a2 += __shfl_down_sync(0xffffffffu, a2, o);
        a3 += __shfl_down_sync(0xffffffffu, a3, o);
    }
    __shared__ float red[4][4];
    if ((t & 31) == 0){ int w=t>>5; red[w][0]=a0; red[w][1]=a1; red[w][2]=a2; red[w][3]=a3; }
    __syncthreads();
    if (t == 0){
        int c4 = cls*4;
        float d0 = bb[c4+0] + red[0][0]+red[1][0]+red[2][0]+red[3][0];
        float d1 = bb[c4+1] + red[0][1]+red[1][1]+red[2][1]+red[3][1];
        float d2 = bb[c4+2] + red[0][2]+red[1][2]+red[2][2]+red[3][2];
        float d3 = bb[c4+3] + red[0][3]+red[1][3]+red[2][3]+red[3][3];
        float px1 = prop[row*4+0], py1 = prop[row*4+1];
        float px2 = prop[row*4+2], py2 = prop[row*4+3];
        float w  = px2 - px1, h = py2 - py1;
        float cx = px1 + 0.5f*w, cy = py1 + 0.5f*h;
        float dx = d0 / 10.0f, dy = d1 / 10.0f;
        float dw = fminf(d2 / 5.0f, SCALE_CLAMP);
        float dh = fminf(d3 / 5.0f, SCALE_CLAMP);
        float pcx = dx*w + cx, pcy = dy*h + cy;
        float pw = expf(dw)*w, ph = expf(dh)*h;
        float x1 = pcx - 0.5f*pw, y1 = pcy - 0.5f*ph;
        float x2 = pcx + 0.5f*pw, y2 = pcy + 0.5f*ph;
        x1 = fminf(fmaxf(x1, 0.f), IMG_W);
        x2 = fminf(fmaxf(x2, 0.f), IMG_W);
        y1 = fminf(fmaxf(y1, 0.f), IMG_H);
        y2 = fminf(fmaxf(y2, 0.f), IMG_H);
        g_boxes[rank*4+0]=x1; g_boxes[rank*4+1]=y1;
        g_boxes[rank*4+2]=x2; g_boxes[rank*4+3]=y2;
        float off = (float)cls * MAX_COORD;
        g_obox[rank*4+0]=x1+off; g_obox[rank*4+1]=y1+off;
        g_obox[rank*4+2]=x2+off; g_obox[rank*4+3]=y2+off;
        g_cls[rank] = cls;
        float p = g_probs[idx];
        bool v = p > SCORE_T;
        g_score[rank] = v ? p : -1.0f;
        g_valid[rank] = v ? 1 : 0;
    }
}

// ---------------- K4: per-class greedy NMS (80 blocks) ----------------
__global__ __launch_bounds__(256) void k_nms(){
    const int c = blockIdx.x;
    const int t = threadIdx.x;
    __shared__ float4 sb[MSEL];
    __shared__ short srk[MSEL];
    __shared__ unsigned char ssup[MSEL];
    __shared__ int s_n;
    __shared__ int wcnt[8];
    if (t==0) s_n = 0;
    __syncthreads();
    int lane = t & 31, wd = t >> 5;
    for (int base=0; base<MSEL; base+=256){
        int i = base + t;
        bool f = g_valid[i] && (g_cls[i] == c);
        unsigned bal = __ballot_sync(0xffffffffu, f);
        if (lane==0) wcnt[wd] = __popc(bal);
        __syncthreads();
        int off = s_n;
        for (int w2=0; w2<wd; w2++) off += wcnt[w2];
        if (f){
            int pos = off + __popc(bal & ((1u<<lane)-1u));
            sb[pos]  = *(const float4*)&g_obox[i*4];
            srk[pos] = (short)i;
            ssup[pos]= 0;
        }
        __syncthreads();
        if (t==0){ int tt=0; for (int w2=0;w2<8;w2++) tt+=wcnt[w2]; s_n += tt; }
        __syncthreads();
    }
    const int n = s_n;
    for (int k=0; k<n; k++){
        __syncthreads();
        if (ssup[k]) continue;
        float4 bk = sb[k];
        float ak = (bk.z - bk.x) * (bk.w - bk.y);
        for (int j=k+1+t; j<n; j+=256){
            if (ssup[j]) continue;
            float4 bj = sb[j];
            float xx1 = fmaxf(bk.x, bj.x), yy1 = fmaxf(bk.y, bj.y);
            float xx2 = fminf(bk.z, bj.z), yy2 = fminf(bk.w, bj.w);
            float inter = fmaxf(xx2-xx1, 0.f) * fmaxf(yy2-yy1, 0.f);
            float aj = (bj.z - bj.x) * (bj.w - bj.y);
            float un = fmaxf(ak + aj - inter, 1e-9f);
            if (inter / un > 0.5f) ssup[j] = 1;
        }
    }
    __syncthreads();
    for (int j=t; j<n; j+=256) if (ssup[j]) g_sup[srk[j]] = 1;
}

// ---------------- K5: final top-100 scan + output ----------------
__device__ __forceinline__ void emit_out(int i, int keep, int pk, int nK, float* out){
    int slot = keep ? pk : (nK + (i - pk));
    if (slot < TOPK){
        out[slot*4+0] = g_boxes[i*4+0];
        out[slot*4+1] = g_boxes[i*4+1];
        out[slot*4+2] = g_boxes[i*4+2];
        out[slot*4+3] = g_boxes[i*4+3];
        out[400+slot] = keep ? g_score[i] : -1.0f;
        out[500+slot] = (float)g_cls[i];
        out[600+slot] = keep ? 1.0f : 0.0f;
    }
}
__global__ void k_out(float* out){
    int t = threadIdx.x;
    __shared__ int warpS[32];
    __shared__ int s_tot;
    int i0 = 2*t, i1 = 2*t+1;
    int k0 = (g_valid[i0] && !g_sup[i0]) ? 1 : 0;
    int k1 = (g_valid[i1] && !g_sup[i1]) ? 1 : 0;
    int ps = k0 + k1;
    int lane = t & 31, wd = t >> 5;
    int v = ps;
    #pragma unroll
    for (int o=1;o<32;o<<=1){ int nn = __shfl_up_sync(0xffffffffu, v, o); if (lane>=o) v += nn; }
    if (lane==31) warpS[wd] = v;
    __syncthreads();
    if (wd==0){
        int w = warpS[lane];
        #pragma unroll
        for (int o=1;o<32;o<<=1){ int nn = __shfl_up_sync(0xffffffffu, w, o); if (lane>=o) w += nn; }
        warpS[lane] = w;
        if (lane==31) s_tot = w;
    }
    __syncthreads();
    int incl = v + ((wd>0) ? warpS[wd-1] : 0);
    int ex0 = incl - ps;
    int nK = s_tot;
    emit_out(i0, k0, ex0, nK, out);
    emit_out(i1, k1, ex0 + k0, nK, out);
}

// ---------------- launch ----------------
extern "C" void kernel_launch(void* const* d_in, const int* in_sizes, int n_in,
                              void* d_out, int out_size){
    const float* x    = (const float*)d_in[0];
    const float* clsw = (const float*)d_in[1];
    const float* clsb = (const float*)d_in[2];
    const float* bw   = (const float*)d_in[3];
    const float* bbias= (const float*)d_in[4];
    const float* prop = (const float*)d_in[5];
    float* out = (float*)d_out;

    k_prep<<<64, 256>>>(bw, out, out_size);
    k_gemm_softmax<<<NROWS/64, 256>>>(x, clsw, clsb);
    k_select<<<1, 1024>>>();
    k_decode<<<MSEL, 128>>>(x, bbias, prop);
    k_nms<<<KCLS, 256>>>();
    k_out<<<1, 1024>>>(out);
}